// round 16
// baseline (speedup 1.0000x reference)
#include <cuda_runtime.h>

#define B_   64
#define C_   768
#define HW_  784      // 28*28
#define HID_ 192      // C/4
#define HW4_ 196      // HW/4  (float4 per (b,c) row)

// scratch (no device allocation allowed)
__device__ float g_pooled[B_ * C_];
__device__ float g_s[B_ * C_];

// ---------------------------------------------------------------------------
// Kernel 1: global average pool. One warp per (b,c) row (196 float4).
// 6 unconditional + 1 predicated LDG.128 per lane -> MLP 7. (proven 28.1us)
// ---------------------------------------------------------------------------
__global__ void pool_kernel(const float* __restrict__ x) {
    unsigned warp = (blockIdx.x * blockDim.x + threadIdx.x) >> 5;   // exact grid
    unsigned lane = threadIdx.x & 31u;

    const float4* p = reinterpret_cast<const float4*>(x) + (size_t)warp * HW4_;
    float4 a0 = p[lane];
    float4 a1 = p[lane + 32];
    float4 a2 = p[lane + 64];
    float4 a3 = p[lane + 96];
    float4 a4 = p[lane + 128];
    float4 a5 = p[lane + 160];
    float extra = 0.f;
    if (lane < 4) {                      // indices 192..195
        float4 v = p[lane + 192];
        extra = (v.x + v.y) + (v.z + v.w);
    }
    float s01 = (a0.x + a0.y) + (a0.z + a0.w) + (a1.x + a1.y) + (a1.z + a1.w);
    float s23 = (a2.x + a2.y) + (a2.z + a2.w) + (a3.x + a3.y) + (a3.z + a3.w);
    float s45 = (a4.x + a4.y) + (a4.z + a4.w) + (a5.x + a5.y) + (a5.z + a5.w);
    float sum = (s01 + s23) + (s45 + extra);

    #pragma unroll
    for (int o = 16; o > 0; o >>= 1)
        sum += __shfl_xor_sync(0xffffffffu, sum, o);
    if (lane == 0)
        g_pooled[warp] = sum * (1.0f / HW_);
}

// ---------------------------------------------------------------------------
// Kernel 2: both FCs in ONE launch. Block per batch (64 blocks, 1024 thr).
//   h = relu(pooled @ w1^T + b1)     [192]  (warp per h, 6 iters)
//   s = hardsigmoid(h @ w2^T + b2)   [768]  (warp per c, 24 iters)
// Pooled row + hidden live in smem; w1/w2 (589 KB each) L2-resident.
// ---------------------------------------------------------------------------
__global__ void __launch_bounds__(1024)
fc_kernel(const float* __restrict__ w1, const float* __restrict__ b1,
          const float* __restrict__ w2, const float* __restrict__ b2) {
    __shared__ float sp[C_];
    __shared__ float sh[HID_];
    const int b = (int)blockIdx.x;
    const unsigned t    = threadIdx.x;
    const unsigned lane = t & 31u;
    const unsigned wid  = t >> 5;           // 0..31

    if (t < C_) sp[t] = g_pooled[b * C_ + t];
    __syncthreads();

    // fc1: 32 warps cover 192 h-outputs (6 per warp)
    #pragma unroll
    for (unsigned h = wid; h < HID_; h += 32) {
        const float4* wv = reinterpret_cast<const float4*>(w1 + h * C_);
        const float4* pv = reinterpret_cast<const float4*>(sp);
        float acc = 0.f;
        #pragma unroll
        for (int k = 0; k < 6; k++) {
            float4 a = pv[lane + 32 * k];
            float4 w = wv[lane + 32 * k];
            acc += a.x * w.x + a.y * w.y + a.z * w.z + a.w * w.w;
        }
        #pragma unroll
        for (int o = 16; o > 0; o >>= 1)
            acc += __shfl_xor_sync(0xffffffffu, acc, o);
        if (lane == 0)
            sh[h] = fmaxf(acc + b1[h], 0.f);
    }
    __syncthreads();

    // fc2: 32 warps cover 768 c-outputs (24 per warp)
    #pragma unroll 4
    for (unsigned c = wid; c < C_; c += 32) {
        const float4* wv = reinterpret_cast<const float4*>(w2 + c * HID_);
        const float4* hv = reinterpret_cast<const float4*>(sh);
        float4 a = hv[lane];
        float4 w = wv[lane];
        float acc = a.x * w.x + a.y * w.y + a.z * w.z + a.w * w.w;
        if (lane < 16) {
            a = hv[lane + 32];
            w = wv[lane + 32];
            acc += a.x * w.x + a.y * w.y + a.z * w.z + a.w * w.w;
        }
        #pragma unroll
        for (int o = 16; o > 0; o >>= 1)
            acc += __shfl_xor_sync(0xffffffffu, acc, o);
        if (lane == 0)
            g_s[b * C_ + c] = __saturatef((acc + b2[c]) * (1.0f / 6.0f) + 0.5f);
    }
}

// ---------------------------------------------------------------------------
// Kernel 3: out = x * s[b,c]. FOUR consecutive float4 (64B) per thread;
// 196 % 4 == 0 so all four share one channel -> one s lookup.
// REVERSED block order harvests the L2-resident tail of x left by pool.
// __ldcs: last-use read. __stcs: evict-first allocate (R4-proven; __stwt
// regressed in R14 -> reverted).
// ---------------------------------------------------------------------------
__global__ void scale_kernel(const float* __restrict__ x, float* __restrict__ out) {
    unsigned j  = (gridDim.x - 1u - blockIdx.x) * blockDim.x + threadIdx.x;
    unsigned f0 = j * 4u;                                   // first float4 idx

    float s = g_s[f0 / HW4_];
    const float4* xp = reinterpret_cast<const float4*>(x);
    float4*       op = reinterpret_cast<float4*>(out);

    float4 v0 = __ldcs(xp + f0);
    float4 v1 = __ldcs(xp + f0 + 1);
    float4 v2 = __ldcs(xp + f0 + 2);
    float4 v3 = __ldcs(xp + f0 + 3);
    v0.x *= s; v0.y *= s; v0.z *= s; v0.w *= s;
    v1.x *= s; v1.y *= s; v1.z *= s; v1.w *= s;
    v2.x *= s; v2.y *= s; v2.z *= s; v2.w *= s;
    v3.x *= s; v3.y *= s; v3.z *= s; v3.w *= s;
    __stcs(op + f0,     v0);
    __stcs(op + f0 + 1, v1);
    __stcs(op + f0 + 2, v2);
    __stcs(op + f0 + 3, v3);
}

// ---------------------------------------------------------------------------
extern "C" void kernel_launch(void* const* d_in, const int* in_sizes, int n_in,
                              void* d_out, int out_size) {
    const float* x  = (const float*)d_in[0];
    const float* w1 = (const float*)d_in[1];
    const float* b1 = (const float*)d_in[2];
    const float* w2 = (const float*)d_in[3];
    const float* b2 = (const float*)d_in[4];
    float* out = (float*)d_out;

    pool_kernel<<<(B_ * C_) / 8, 256>>>(x);           // 6144 blocks, warp/row
    fc_kernel<<<B_, 1024>>>(w1, b1, w2, b2);          // 64 blocks, both layers
    // scale: 9,633,792 float4 / 4 per thread / 256 = 9408 blocks (exact)
    const unsigned nthreads4 = (unsigned)(B_ * C_ * HW4_) / 4u;
    scale_kernel<<<nthreads4 / 256, 256>>>(x, out);
}

// round 17
// speedup vs baseline: 1.2207x; 1.2207x over previous
#include <cuda_runtime.h>

#define B_   64
#define C_   768
#define HW_  784      // 28*28
#define HID_ 192      // C/4
#define HW4_ 196      // HW/4  (float4 per (b,c) row)

// scratch (no device allocation allowed)
__device__ float g_pooled[B_ * C_];
__device__ float g_h[B_ * HID_];
__device__ float g_s[B_ * C_];

// ---------------------------------------------------------------------------
// Kernel 1: global average pool. One warp per (b,c) row (196 float4).
// Warp-strided -> fully coalesced; MLP 7. (proven 27-28us, 73.9% DRAM)
// ---------------------------------------------------------------------------
__global__ void pool_kernel(const float* __restrict__ x) {
    unsigned warp = (blockIdx.x * blockDim.x + threadIdx.x) >> 5;   // exact grid
    unsigned lane = threadIdx.x & 31u;

    const float4* p = reinterpret_cast<const float4*>(x) + (size_t)warp * HW4_;
    float4 a0 = p[lane];
    float4 a1 = p[lane + 32];
    float4 a2 = p[lane + 64];
    float4 a3 = p[lane + 96];
    float4 a4 = p[lane + 128];
    float4 a5 = p[lane + 160];
    float extra = 0.f;
    if (lane < 4) {                      // indices 192..195
        float4 v = p[lane + 192];
        extra = (v.x + v.y) + (v.z + v.w);
    }
    float s01 = (a0.x + a0.y) + (a0.z + a0.w) + (a1.x + a1.y) + (a1.z + a1.w);
    float s23 = (a2.x + a2.y) + (a2.z + a2.w) + (a3.x + a3.y) + (a3.z + a3.w);
    float s45 = (a4.x + a4.y) + (a4.z + a4.w) + (a5.x + a5.y) + (a5.z + a5.w);
    float sum = (s01 + s23) + (s45 + extra);

    #pragma unroll
    for (int o = 16; o > 0; o >>= 1)
        sum += __shfl_xor_sync(0xffffffffu, sum, o);
    if (lane == 0)
        g_pooled[warp] = sum * (1.0f / HW_);
}

// ---------------------------------------------------------------------------
// Kernel 2a: h = relu(pooled @ w1^T + b1). One warp per (b,h) output. (R4)
// ---------------------------------------------------------------------------
__global__ void fc1_kernel(const float* __restrict__ w1, const float* __restrict__ b1) {
    unsigned gw   = (blockIdx.x * blockDim.x + threadIdx.x) >> 5;   // 0..12287
    unsigned lane = threadIdx.x & 31u;
    unsigned b = gw / HID_;
    unsigned h = gw % HID_;

    const float4* pv = reinterpret_cast<const float4*>(g_pooled + b * C_);
    const float4* wv = reinterpret_cast<const float4*>(w1 + h * C_);
    float acc = 0.f;
    #pragma unroll
    for (int k = 0; k < 6; k++) {
        float4 a = pv[lane + 32 * k];
        float4 w = wv[lane + 32 * k];
        acc += a.x * w.x + a.y * w.y + a.z * w.z + a.w * w.w;
    }
    #pragma unroll
    for (int o = 16; o > 0; o >>= 1)
        acc += __shfl_xor_sync(0xffffffffu, acc, o);
    if (lane == 0)
        g_h[gw] = fmaxf(acc + b1[h], 0.f);
}

// ---------------------------------------------------------------------------
// Kernel 2b: s = hardsigmoid(h @ w2^T + b2). One warp per (b,c) output. (R4)
// ---------------------------------------------------------------------------
__global__ void fc2_kernel(const float* __restrict__ w2, const float* __restrict__ b2) {
    unsigned gw   = (blockIdx.x * blockDim.x + threadIdx.x) >> 5;   // 0..49151
    unsigned lane = threadIdx.x & 31u;
    unsigned b = gw / C_;
    unsigned c = gw % C_;

    const float4* hv = reinterpret_cast<const float4*>(g_h + b * HID_);
    const float4* wv = reinterpret_cast<const float4*>(w2 + c * HID_);
    float4 a = hv[lane];
    float4 w = wv[lane];
    float acc = a.x * w.x + a.y * w.y + a.z * w.z + a.w * w.w;
    if (lane < 16) {
        a = hv[lane + 32];
        w = wv[lane + 32];
        acc += a.x * w.x + a.y * w.y + a.z * w.z + a.w * w.w;
    }
    #pragma unroll
    for (int o = 16; o > 0; o >>= 1)
        acc += __shfl_xor_sync(0xffffffffu, acc, o);
    if (lane == 0)
        g_s[gw] = __saturatef((acc + b2[c]) * (1.0f / 6.0f) + 0.5f);
}

// ---------------------------------------------------------------------------
// Kernel 3: out = x * s[b,c].  BLOCK-STRIDED mapping: block owns 1024
// consecutive float4 (16 KB); thread t handles base + t + k*256, k=0..3.
// Every LDG.128/STG.128 is fully coalesced (4 lines/warp) — fixes the
// 2-4x L1tex wavefront inflation of the consecutive-per-thread variants.
// s looked up per element (f/196 -> IMAD magic; ALU has headroom).
// REVERSED block order + __ldcs/__stcs keep the L2 tail-residency harvest.
// ---------------------------------------------------------------------------
__global__ void scale_kernel(const float* __restrict__ x, float* __restrict__ out) {
    unsigned blk  = gridDim.x - 1u - blockIdx.x;          // reversed
    unsigned base = blk * 1024u + threadIdx.x;            // float4 index, k*256 stride
    const float4* xp = reinterpret_cast<const float4*>(x);
    float4*       op = reinterpret_cast<float4*>(out);

    unsigned f0 = base;
    unsigned f1 = base + 256u;
    unsigned f2 = base + 512u;
    unsigned f3 = base + 768u;

    float s0 = __ldg(&g_s[f0 / HW4_]);
    float s1 = __ldg(&g_s[f1 / HW4_]);
    float s2 = __ldg(&g_s[f2 / HW4_]);
    float s3 = __ldg(&g_s[f3 / HW4_]);

    float4 v0 = __ldcs(xp + f0);
    float4 v1 = __ldcs(xp + f1);
    float4 v2 = __ldcs(xp + f2);
    float4 v3 = __ldcs(xp + f3);

    v0.x *= s0; v0.y *= s0; v0.z *= s0; v0.w *= s0;
    v1.x *= s1; v1.y *= s1; v1.z *= s1; v1.w *= s1;
    v2.x *= s2; v2.y *= s2; v2.z *= s2; v2.w *= s2;
    v3.x *= s3; v3.y *= s3; v3.z *= s3; v3.w *= s3;

    __stcs(op + f0, v0);
    __stcs(op + f1, v1);
    __stcs(op + f2, v2);
    __stcs(op + f3, v3);
}

// ---------------------------------------------------------------------------
extern "C" void kernel_launch(void* const* d_in, const int* in_sizes, int n_in,
                              void* d_out, int out_size) {
    const float* x  = (const float*)d_in[0];
    const float* w1 = (const float*)d_in[1];
    const float* b1 = (const float*)d_in[2];
    const float* w2 = (const float*)d_in[3];
    const float* b2 = (const float*)d_in[4];
    float* out = (float*)d_out;

    pool_kernel<<<(B_ * C_) / 8, 256>>>(x);              // 6144 blocks, warp/row
    fc1_kernel<<<(B_ * HID_) / 8, 256>>>(w1, b1);        // 1536 blocks, warp/out
    fc2_kernel<<<(B_ * C_) / 8, 256>>>(w2, b2);          // 6144 blocks, warp/out
    // scale: 9,633,792 float4 / 1024 per block = 9408 blocks (exact)
    scale_kernel<<<(unsigned)(B_ * C_ * HW4_) / 1024u, 256>>>(x, out);
}